// round 9
// baseline (speedup 1.0000x reference)
#include <cuda_runtime.h>
#include <cuda_fp16.h>
#include <math.h>

#define N_NODES 100000
#define N_EDGES 1600000
#define HID 32

#define SCAN_T 512
#define SCAN_ITEMS 8
#define SCAN_PART (SCAN_T * SCAN_ITEMS)                 // 4096
#define N_PARTS ((N_NODES + SCAN_PART - 1) / SCAN_PART) // 25

// ---------------- device scratch ----------------
__device__ float4 g_h  [N_NODES * 8];
__device__ float4 g_A  [N_NODES * 8];
__device__ unsigned long long g_Bh[N_NODES * 8];   // fp16 B table: 8B per (node, comp)
__device__ float4 g_agg[N_NODES * 8];
__device__ float4 g_pos4[N_NODES];
__device__ int2   g_epack[N_EDGES];
// combined zero region: [0, N_NODES) = hist; [N_NODES, +2*N_PARTS) = scan state
__device__ __align__(8) int g_zero[N_NODES + 2 * N_PARTS];
__device__ int    g_off [N_NODES];
__device__ int    g_cur [N_NODES];

// folded matrices/vectors
__device__ float  c_Pa[3][1024], c_Pb[3][1024], c_P1[3][1024], c_P2[3][1024], c_Po[1024];
__device__ float  c_qa[3][32],  c_qb[3][32],  c_q1[3][32],  c_v[3][32],  c_qo[32];

// ---------------- helpers ----------------
__device__ __forceinline__ float4 fma4(float f, float4 w, float4 a) {
    a.x = fmaf(f, w.x, a.x); a.y = fmaf(f, w.y, a.y);
    a.z = fmaf(f, w.z, a.z); a.w = fmaf(f, w.w, a.w);
    return a;
}
__device__ __forceinline__ float4 add4(float4 a, float4 b) {
    a.x += b.x; a.y += b.y; a.z += b.z; a.w += b.w; return a;
}
__device__ __forceinline__ float4 relu4(float4 v) {
    v.x = fmaxf(v.x, 0.f); v.y = fmaxf(v.y, 0.f);
    v.z = fmaxf(v.z, 0.f); v.w = fmaxf(v.w, 0.f); return v;
}
#define COMP(v, c) ((c) == 0 ? (v).x : (c) == 1 ? (v).y : (c) == 2 ? (v).z : (v).w)

__device__ __forceinline__ ulonglong2 pack4(float4 v) {
    ulonglong2 r;
    asm("mov.b64 %0, {%1, %2};" : "=l"(r.x) : "f"(v.x), "f"(v.y));
    asm("mov.b64 %0, {%1, %2};" : "=l"(r.y) : "f"(v.z), "f"(v.w));
    return r;
}
__device__ __forceinline__ float4 unpack4(ulonglong2 v) {
    float4 r;
    asm("mov.b64 {%0, %1}, %2;" : "=f"(r.x), "=f"(r.y) : "l"(v.x));
    asm("mov.b64 {%0, %1}, %2;" : "=f"(r.z), "=f"(r.w) : "l"(v.y));
    return r;
}
__device__ __forceinline__ unsigned long long f4_to_h4(float4 v) {
    __half2 h0 = __floats2half2_rn(v.x, v.y);
    __half2 h1 = __floats2half2_rn(v.z, v.w);
    unsigned lo = *reinterpret_cast<unsigned*>(&h0);
    unsigned hi = *reinterpret_cast<unsigned*>(&h1);
    return (unsigned long long)lo | ((unsigned long long)hi << 32);
}
__device__ __forceinline__ float4 h4_to_f4(unsigned long long v) {
    unsigned lo = (unsigned)v, hi = (unsigned)(v >> 32);
    __half2 h0 = *reinterpret_cast<__half2*>(&lo);
    __half2 h1 = *reinterpret_cast<__half2*>(&hi);
    float2 f0 = __half22float2(h0), f1 = __half22float2(h1);
    return make_float4(f0.x, f0.y, f1.x, f1.y);
}

__device__ __forceinline__ void gemv32(const float4* __restrict__ sW,
                                       const float4* xr, ulonglong2* acc) {
#pragma unroll
    for (int k = 0; k < 32; k++) {
        float f = COMP(xr[k >> 2], k & 3);
        unsigned long long f2;
        asm("mov.b64 %0, {%1, %1};" : "=l"(f2) : "f"(f));
        const ulonglong2* w = (const ulonglong2*)(sW + k * 8);
#pragma unroll
        for (int i = 0; i < 8; i++) {
            ulonglong2 wv = w[i];
            asm("fma.rn.f32x2 %0, %1, %2, %0;" : "+l"(acc[i].x) : "l"(f2), "l"(wv.x));
            asm("fma.rn.f32x2 %0, %1, %2, %0;" : "+l"(acc[i].y) : "l"(f2), "l"(wv.y));
        }
    }
}

// int64 edge values < 1e5 -> odd 32-bit words all zero; int32 layout -> random nonzero
__device__ __forceinline__ int detect_i64(const int* ei32) {
    int v = ei32[2 * (threadIdx.x & 31) + 1];
    unsigned m = __ballot_sync(0xffffffffu, v != 0);
    return m == 0;
}

// ---------------- decode: dst histogram + pos packing ----------------
__global__ void decode_kernel(const void* ei, const float* __restrict__ pos) {
    int i64 = detect_i64((const int*)ei);
    int e = blockIdx.x * blockDim.x + threadIdx.x;
    if (e < N_NODES)
        g_pos4[e] = make_float4(pos[e * 3 + 0], pos[e * 3 + 1], pos[e * 3 + 2], 0.f);
    if (e >= N_EDGES) return;
    int dst;
    if (i64) dst = (int)((const long long*)ei)[N_EDGES + e];
    else     dst = ((const int*)ei)[N_EDGES + e];
    atomicAdd(&g_zero[dst], 1);
}

// ---------------- scan (decoupled lookback) + precompute, one launch ----------------
__global__ void __launch_bounds__(SCAN_T) scanpre_kernel(
    const float* __restrict__ enc_w2, const float* __restrict__ enc_b2,
    const float* __restrict__ msg_w1, const float* __restrict__ msg_b1,
    const float* __restrict__ msg_w2, const float* __restrict__ msg_b2,
    const float* __restrict__ upd_w1, const float* __restrict__ upd_b1,
    const float* __restrict__ upd_w2, const float* __restrict__ upd_b2,
    const float* __restrict__ out_w, const float* __restrict__ out_b) {
    int t = threadIdx.x;
    if (blockIdx.x >= N_PARTS) {
        int b = blockIdx.x - N_PARTS;
        if (b < 13) {
            int l = (b < 12) ? (b % 3) : 2;
            int kind = (b < 12) ? (b / 3) : 4;
            const float* Wp = (l == 0) ? enc_w2 : upd_w2 + (size_t)(l - 1) * 1024;
            const float* L; const float* R; float* P;
            switch (kind) {
                case 0: L = Wp;                      R = msg_w1 + (size_t)l * 2080;        P = c_Pa[l]; break;
                case 1: L = Wp;                      R = msg_w1 + (size_t)l * 2080 + 1024; P = c_Pb[l]; break;
                case 2: L = Wp;                      R = upd_w1 + (size_t)l * 2048;        P = c_P1[l]; break;
                case 3: L = msg_w2 + (size_t)l*1024; R = upd_w1 + (size_t)l * 2048 + 1024; P = c_P2[l]; break;
                default: L = upd_w2 + 2048;          R = out_w;                            P = c_Po;    break;
            }
            for (int e = t; e < 1024; e += SCAN_T) {
                int i = e >> 5, j = e & 31;
                float s = 0.f;
                for (int k = 0; k < 32; k++) s = fmaf(L[i * 32 + k], R[k * 32 + j], s);
                P[e] = s;
            }
        } else {
            for (int e = t; e < 416; e += SCAN_T) {
                int vid = e >> 5, j = e & 31;
                int l = vid % 3;
                const float* cp = (l == 0) ? enc_b2 : upd_b2 + (size_t)(l - 1) * 32;
                float s = 0.f;
                if (vid < 3) {
                    const float* R = msg_w1 + (size_t)l * 2080;
                    for (int k = 0; k < 32; k++) s = fmaf(cp[k], R[k * 32 + j], s);
                    c_qa[l][j] = s;
                } else if (vid < 6) {
                    const float* R = msg_w1 + (size_t)l * 2080 + 1024;
                    for (int k = 0; k < 32; k++) s = fmaf(cp[k], R[k * 32 + j], s);
                    c_qb[l][j] = s;
                } else if (vid < 9) {
                    const float* R = upd_w1 + (size_t)l * 2048;
                    for (int k = 0; k < 32; k++) s = fmaf(cp[k], R[k * 32 + j], s);
                    c_q1[l][j] = s + upd_b1[l * 32 + j];
                } else if (vid < 12) {
                    const float* R = upd_w1 + (size_t)l * 2048 + 1024;
                    const float* mb = msg_b2 + (size_t)l * 32;
                    for (int k = 0; k < 32; k++) s = fmaf(mb[k], R[k * 32 + j], s);
                    c_v[l][j] = s;
                } else {
                    const float* ub = upd_b2 + 2 * 32;
                    for (int k = 0; k < 32; k++) s = fmaf(ub[k], out_w[k * 32 + j], s);
                    c_qo[j] = s + out_b[j];
                }
            }
        }
        return;
    }

    // ---- scan part ----
    __shared__ int s[SCAN_T];
    __shared__ int s_prefix;
    unsigned long long* state = (unsigned long long*)&g_zero[N_NODES];
    int part = blockIdx.x;
    int base = part * SCAN_PART + t * SCAN_ITEMS;
    int v[SCAN_ITEMS];
    int tsum = 0;
#pragma unroll
    for (int j = 0; j < SCAN_ITEMS; j++) {
        int idx = base + j;
        v[j] = (idx < N_NODES) ? g_zero[idx] : 0;
        tsum += v[j];
    }
    s[t] = tsum;
    __syncthreads();
#pragma unroll
    for (int off = 1; off < SCAN_T; off <<= 1) {
        int tt = (t >= off) ? s[t - off] : 0;
        __syncthreads();
        s[t] += tt;
        __syncthreads();
    }
    int texcl = s[t] - tsum;
    int btotal = s[SCAN_T - 1];

    if (t == 0) {
        if (part == 0) {
            s_prefix = 0;
            atomicExch(&state[0], (2ULL << 32) | (unsigned)btotal);
        } else {
            atomicExch(&state[part], (1ULL << 32) | (unsigned)btotal);
            int pref = 0;
            int p = part - 1;
            while (true) {
                unsigned long long st;
                do { st = atomicAdd(&state[p], 0ULL); } while ((st >> 32) == 0);
                pref += (int)(unsigned)st;
                if ((st >> 32) == 2) break;
                p--;
            }
            s_prefix = pref;
            atomicExch(&state[part], (2ULL << 32) | (unsigned)(pref + btotal));
        }
    }
    __syncthreads();
    int excl = s_prefix + texcl;
#pragma unroll
    for (int j = 0; j < SCAN_ITEMS; j++) {
        int idx = base + j;
        if (idx < N_NODES) { g_off[idx] = excl; g_cur[idx] = excl; }
        excl += v[j];
    }
}

// ---------------- scatter edges into CSR order (by dst) ----------------
__global__ void scatter_kernel(const void* ei) {
    int i64 = detect_i64((const int*)ei);
    int e = blockIdx.x * blockDim.x + threadIdx.x;
    if (e >= N_EDGES) return;
    int src, dst;
    if (i64) {
        const long long* p = (const long long*)ei;
        src = (int)p[e]; dst = (int)p[N_EDGES + e];
    } else {
        const int* p = (const int*)ei;
        src = p[e]; dst = p[N_EDGES + e];
    }
    float4 pd = __ldg(&g_pos4[dst]);
    float4 ps = __ldg(&g_pos4[src]);
    float dx = pd.x - ps.x, dy = pd.y - ps.y, dz = pd.z - ps.z;
    float dist = sqrtf(dx * dx + dy * dy + dz * dz);
    int p = atomicAdd(&g_cur[dst], 1);
    g_epack[p] = make_int2(src, __float_as_int(dist));
}

// ---------------- encoder: h = relu(feat@w1+b1); A=h@Pa0+qa0; B=h@Pb0+qb0 ----------------
__global__ void __launch_bounds__(128, 5) encoder_kernel(
    const float* __restrict__ feat,
    const float* __restrict__ w1, const float* __restrict__ b1) {
    __shared__ float  s_feat[128 * 33];
    __shared__ float4 s_w1[64 * 8];
    __shared__ float4 s_pa[256], s_pb[256];
    __shared__ float4 s_b1[8], s_qa[8], s_qb[8];
    for (int i = threadIdx.x; i < 512; i += 128) s_w1[i] = ((const float4*)w1)[i];
    for (int i = threadIdx.x; i < 256; i += 128) {
        s_pa[i] = ((const float4*)c_Pa[0])[i];
        s_pb[i] = ((const float4*)c_Pb[0])[i];
    }
    if (threadIdx.x < 8) {
        s_b1[threadIdx.x] = ((const float4*)b1)[threadIdx.x];
        s_qa[threadIdx.x] = ((const float4*)c_qa[0])[threadIdx.x];
        s_qb[threadIdx.x] = ((const float4*)c_qb[0])[threadIdx.x];
    }
    __syncthreads();
    int base = blockIdx.x * 128;
    int n = base + threadIdx.x;
    bool act = (n < N_NODES);

    ulonglong2 hacc[8];
#pragma unroll
    for (int i = 0; i < 8; i++) hacc[i] = pack4(s_b1[i]);

#pragma unroll
    for (int half = 0; half < 2; half++) {
        for (int j = threadIdx.x; j < 128 * 32; j += 128) {
            int r = j >> 5, col = j & 31;
            int nn = base + r;
            s_feat[r * 33 + col] =
                (nn < N_NODES) ? feat[(size_t)nn * 64 + half * 32 + col] : 0.f;
        }
        __syncthreads();
        const float* frow = &s_feat[threadIdx.x * 33];
#pragma unroll 8
        for (int k = 0; k < 32; k++) {
            float f = frow[k];
            unsigned long long f2;
            asm("mov.b64 %0, {%1, %1};" : "=l"(f2) : "f"(f));
            const ulonglong2* w = (const ulonglong2*)(s_w1 + (half * 32 + k) * 8);
#pragma unroll
            for (int i = 0; i < 8; i++) {
                ulonglong2 wv = w[i];
                asm("fma.rn.f32x2 %0, %1, %2, %0;" : "+l"(hacc[i].x) : "l"(f2), "l"(wv.x));
                asm("fma.rn.f32x2 %0, %1, %2, %0;" : "+l"(hacc[i].y) : "l"(f2), "l"(wv.y));
            }
        }
        __syncthreads();
    }
    float4 h[8];
#pragma unroll
    for (int i = 0; i < 8; i++) h[i] = relu4(unpack4(hacc[i]));

    ulonglong2 a[8], b[8];
#pragma unroll
    for (int i = 0; i < 8; i++) { a[i] = pack4(s_qa[i]); b[i] = pack4(s_qb[i]); }
    gemv32(s_pa, h, a);
    gemv32(s_pb, h, b);

    if (act) {
        ulonglong2* ph = (ulonglong2*)&g_h[(size_t)n * 8];
        ulonglong2* pa = (ulonglong2*)&g_A[(size_t)n * 8];
#pragma unroll
        for (int i = 0; i < 8; i++) {
            ph[i] = pack4(h[i]);
            pa[i] = a[i];
            g_Bh[(size_t)n * 8 + i] = f4_to_h4(unpack4(b[i]));
        }
    }
}

// ---------------- per layer: agg[n] = sum_e relu(A[n] + B[src_e] + d_e*c + b1) ----------------
__global__ void __launch_bounds__(256) agg_kernel(
    const float* __restrict__ w1c, const float* __restrict__ b1) {
    int n = (blockIdx.x * 256 + threadIdx.x) >> 5;
    if (n >= N_NODES) return;
    int lane = threadIdx.x & 31;
    int c = lane & 7;
    int slot = lane >> 3;

    float4 cv = __ldg(((const float4*)w1c) + c);
    float4 bb = __ldg(((const float4*)b1) + c);

    int start = __ldg(&g_off[n]);
    int end = start + __ldg(&g_zero[n]);   // g_zero = hist

    float4 ab = add4(g_A[(size_t)n * 8 + c], bb);
    float4 acc0 = make_float4(0.f, 0.f, 0.f, 0.f);
    float4 acc1 = make_float4(0.f, 0.f, 0.f, 0.f);

    int i = start + slot;
    for (; i + 4 < end; i += 8) {
        int2 sd0 = __ldg(&g_epack[i]);
        int2 sd1 = __ldg(&g_epack[i + 4]);
        float4 b0 = h4_to_f4(__ldg(&g_Bh[(size_t)sd0.x * 8 + c]));
        float4 b1v = h4_to_f4(__ldg(&g_Bh[(size_t)sd1.x * 8 + c]));
        acc0 = add4(acc0, relu4(fma4(__int_as_float(sd0.y), cv, add4(ab, b0))));
        acc1 = add4(acc1, relu4(fma4(__int_as_float(sd1.y), cv, add4(ab, b1v))));
    }
    if (i < end) {
        int2 sd = __ldg(&g_epack[i]);
        float4 b = h4_to_f4(__ldg(&g_Bh[(size_t)sd.x * 8 + c]));
        acc0 = add4(acc0, relu4(fma4(__int_as_float(sd.y), cv, add4(ab, b))));
    }
    float4 acc = add4(acc0, acc1);
#pragma unroll
    for (int m = 8; m <= 16; m <<= 1) {
        acc.x += __shfl_xor_sync(0xffffffffu, acc.x, m);
        acc.y += __shfl_xor_sync(0xffffffffu, acc.y, m);
        acc.z += __shfl_xor_sync(0xffffffffu, acc.z, m);
        acc.w += __shfl_xor_sync(0xffffffffu, acc.w, m);
    }
    if (lane < 8) g_agg[(size_t)n * 8 + lane] = acc;
}

// ---------------- per layer update (folded) ----------------
__global__ void __launch_bounds__(128, 5) update_kernel(int l, int last, float* __restrict__ outp) {
    __shared__ float4 s_p1[256], s_p2[256], s_pc[256], s_pd[256];
    __shared__ float4 s_q1[8], s_v[8], s_qc[8], s_qd[8];
    {
        const float* P1 = c_P1[l];
        const float* P2 = c_P2[l];
        const float* Pc = last ? c_Po : c_Pa[l + 1 < 3 ? l + 1 : 0];
        const float* Pd = last ? c_Po : c_Pb[l + 1 < 3 ? l + 1 : 0];
        for (int i = threadIdx.x; i < 256; i += 128) {
            s_p1[i] = ((const float4*)P1)[i];
            s_p2[i] = ((const float4*)P2)[i];
            s_pc[i] = ((const float4*)Pc)[i];
            s_pd[i] = ((const float4*)Pd)[i];
        }
        if (threadIdx.x < 8) {
            s_q1[threadIdx.x] = ((const float4*)c_q1[l])[threadIdx.x];
            s_v[threadIdx.x]  = ((const float4*)c_v[l])[threadIdx.x];
            const float* qc = last ? c_qo : c_qa[l + 1 < 3 ? l + 1 : 0];
            const float* qd = last ? c_qo : c_qb[l + 1 < 3 ? l + 1 : 0];
            s_qc[threadIdx.x] = ((const float4*)qc)[threadIdx.x];
            s_qd[threadIdx.x] = ((const float4*)qd)[threadIdx.x];
        }
    }
    __syncthreads();
    int n = blockIdx.x * blockDim.x + threadIdx.x;
    if (n >= N_NODES) return;

    float deg = (float)g_zero[n];
    ulonglong2 uacc[8];
#pragma unroll
    for (int i = 0; i < 8; i++) {
        float4 q = s_q1[i], vv = s_v[i];
        uacc[i] = pack4(make_float4(fmaf(deg, vv.x, q.x), fmaf(deg, vv.y, q.y),
                                    fmaf(deg, vv.z, q.z), fmaf(deg, vv.w, q.w)));
    }
    float4 hr[8];
#pragma unroll
    for (int i = 0; i < 8; i++) hr[i] = g_h[(size_t)n * 8 + i];
    gemv32(s_p1, hr, uacc);
    float4 ar[8];
#pragma unroll
    for (int i = 0; i < 8; i++) ar[i] = g_agg[(size_t)n * 8 + i];
    gemv32(s_p2, ar, uacc);

    float4 u[8];
#pragma unroll
    for (int i = 0; i < 8; i++) u[i] = relu4(unpack4(uacc[i]));

    ulonglong2 cacc[8];
#pragma unroll
    for (int i = 0; i < 8; i++) cacc[i] = pack4(s_qc[i]);
    gemv32(s_pc, u, cacc);

    if (!last) {
        ulonglong2 dacc[8];
#pragma unroll
        for (int i = 0; i < 8; i++) dacc[i] = pack4(s_qd[i]);
        gemv32(s_pd, u, dacc);
        ulonglong2* ph = (ulonglong2*)&g_h[(size_t)n * 8];
        ulonglong2* pa = (ulonglong2*)&g_A[(size_t)n * 8];
#pragma unroll
        for (int i = 0; i < 8; i++) {
            ph[i] = pack4(u[i]);
            pa[i] = cacc[i];
            g_Bh[(size_t)n * 8 + i] = f4_to_h4(unpack4(dacc[i]));
        }
    } else {
        ulonglong2* orow = (ulonglong2*)(outp + (size_t)n * 32);
#pragma unroll
        for (int i = 0; i < 8; i++) orow[i] = cacc[i];
    }
}

// ---------------- launch ----------------
extern "C" void kernel_launch(void* const* d_in, const int* in_sizes, int n_in,
                              void* d_out, int out_size) {
    const float* node_feat = (const float*)d_in[0];
    const float* pos       = (const float*)d_in[1];
    const void*  ei        = d_in[2];
    const float* enc_w1    = (const float*)d_in[3];
    const float* enc_b1    = (const float*)d_in[4];
    const float* enc_w2    = (const float*)d_in[5];
    const float* enc_b2    = (const float*)d_in[6];
    const float* msg_w1    = (const float*)d_in[7];
    const float* msg_b1    = (const float*)d_in[8];
    const float* msg_w2    = (const float*)d_in[9];
    const float* msg_b2    = (const float*)d_in[10];
    const float* upd_w1    = (const float*)d_in[11];
    const float* upd_b1    = (const float*)d_in[12];
    const float* upd_w2    = (const float*)d_in[13];
    const float* upd_b2    = (const float*)d_in[14];
    const float* out_w     = (const float*)d_in[15];
    const float* out_b     = (const float*)d_in[16];
    float* out = (float*)d_out;

    const int NODE_BLOCKS = (N_NODES + 127) / 128;
    const int EDGE_BLOCKS = (N_EDGES + 255) / 256;
    const int AGG_BLOCKS  = (N_NODES * 32 + 255) / 256;

    // single memset node: hist + scan state
    void* p_zero = nullptr;
    cudaGetSymbolAddress(&p_zero, g_zero);
    cudaMemsetAsync(p_zero, 0, (N_NODES + 2 * N_PARTS) * sizeof(int), 0);

    decode_kernel<<<EDGE_BLOCKS, 256>>>(ei, pos);
    scanpre_kernel<<<N_PARTS + 14, SCAN_T>>>(enc_w2, enc_b2,
        msg_w1, msg_b1, msg_w2, msg_b2, upd_w1, upd_b1, upd_w2, upd_b2, out_w, out_b);
    scatter_kernel<<<EDGE_BLOCKS, 256>>>(ei);
    encoder_kernel<<<NODE_BLOCKS, 128>>>(node_feat, enc_w1, enc_b1);

    for (int l = 0; l < 3; l++) {
        const float* w1 = msg_w1 + (size_t)l * 65 * 32;
        agg_kernel<<<AGG_BLOCKS, 256>>>(w1 + 64 * 32, msg_b1 + (size_t)l * 32);
        update_kernel<<<NODE_BLOCKS, 128>>>(l, l == 2, out);
    }
}

// round 10
// speedup vs baseline: 1.0881x; 1.0881x over previous
#include <cuda_runtime.h>
#include <cuda_fp16.h>
#include <math.h>

#define N_NODES 100000
#define N_EDGES 1600000
#define HID 32

#define SCAN_T 512
#define SCAN_ITEMS 8
#define SCAN_PART (SCAN_T * SCAN_ITEMS)                 // 4096
#define N_PARTS ((N_NODES + SCAN_PART - 1) / SCAN_PART) // 25

// ---------------- device scratch ----------------
__device__ float4 g_h  [N_NODES * 8];
__device__ float4 g_A  [N_NODES * 8];
__device__ unsigned long long g_Bh[N_NODES * 8];   // fp16 B table
__device__ float4 g_agg[N_NODES * 8];
__device__ float4 g_pos4[N_NODES];
__device__ int2   g_epack[N_EDGES];
// combined zero region: [0, N_NODES) = hist; [N_NODES, +2*N_PARTS) = scan state
__device__ __align__(8) int g_zero[N_NODES + 2 * N_PARTS];
__device__ int    g_off [N_NODES];
__device__ int    g_cur [N_NODES];

// folded matrices/vectors
__device__ float  c_Pa[3][1024], c_Pb[3][1024], c_P1[3][1024], c_P2[3][1024], c_Po[1024];
__device__ float  c_qa[3][32],  c_qb[3][32],  c_q1[3][32],  c_v[3][32],  c_qo[32];

// ---------------- helpers ----------------
__device__ __forceinline__ float4 fma4(float f, float4 w, float4 a) {
    a.x = fmaf(f, w.x, a.x); a.y = fmaf(f, w.y, a.y);
    a.z = fmaf(f, w.z, a.z); a.w = fmaf(f, w.w, a.w);
    return a;
}
__device__ __forceinline__ float4 add4(float4 a, float4 b) {
    a.x += b.x; a.y += b.y; a.z += b.z; a.w += b.w; return a;
}
__device__ __forceinline__ float4 relu4(float4 v) {
    v.x = fmaxf(v.x, 0.f); v.y = fmaxf(v.y, 0.f);
    v.z = fmaxf(v.z, 0.f); v.w = fmaxf(v.w, 0.f); return v;
}
#define COMP(v, c) ((c) == 0 ? (v).x : (c) == 1 ? (v).y : (c) == 2 ? (v).z : (v).w)

__device__ __forceinline__ ulonglong2 pack4(float4 v) {
    ulonglong2 r;
    asm("mov.b64 %0, {%1, %2};" : "=l"(r.x) : "f"(v.x), "f"(v.y));
    asm("mov.b64 %0, {%1, %2};" : "=l"(r.y) : "f"(v.z), "f"(v.w));
    return r;
}
__device__ __forceinline__ float4 unpack4(ulonglong2 v) {
    float4 r;
    asm("mov.b64 {%0, %1}, %2;" : "=f"(r.x), "=f"(r.y) : "l"(v.x));
    asm("mov.b64 {%0, %1}, %2;" : "=f"(r.z), "=f"(r.w) : "l"(v.y));
    return r;
}
__device__ __forceinline__ unsigned long long f4_to_h4(float4 v) {
    __half2 h0 = __floats2half2_rn(v.x, v.y);
    __half2 h1 = __floats2half2_rn(v.z, v.w);
    unsigned lo = *reinterpret_cast<unsigned*>(&h0);
    unsigned hi = *reinterpret_cast<unsigned*>(&h1);
    return (unsigned long long)lo | ((unsigned long long)hi << 32);
}
__device__ __forceinline__ float4 h4_to_f4(unsigned long long v) {
    unsigned lo = (unsigned)v, hi = (unsigned)(v >> 32);
    __half2 h0 = *reinterpret_cast<__half2*>(&lo);
    __half2 h1 = *reinterpret_cast<__half2*>(&hi);
    float2 f0 = __half22float2(h0), f1 = __half22float2(h1);
    return make_float4(f0.x, f0.y, f1.x, f1.y);
}

__device__ __forceinline__ void gemv32(const float4* __restrict__ sW,
                                       const float4* xr, ulonglong2* acc) {
#pragma unroll
    for (int k = 0; k < 32; k++) {
        float f = COMP(xr[k >> 2], k & 3);
        unsigned long long f2;
        asm("mov.b64 %0, {%1, %1};" : "=l"(f2) : "f"(f));
        const ulonglong2* w = (const ulonglong2*)(sW + k * 8);
#pragma unroll
        for (int i = 0; i < 8; i++) {
            ulonglong2 wv = w[i];
            asm("fma.rn.f32x2 %0, %1, %2, %0;" : "+l"(acc[i].x) : "l"(f2), "l"(wv.x));
            asm("fma.rn.f32x2 %0, %1, %2, %0;" : "+l"(acc[i].y) : "l"(f2), "l"(wv.y));
        }
    }
}

// int64 edge values < 1e5 -> odd 32-bit words all zero; int32 layout -> random nonzero
__device__ __forceinline__ int detect_i64(const int* ei32) {
    int v = ei32[2 * (threadIdx.x & 31) + 1];
    unsigned m = __ballot_sync(0xffffffffu, v != 0);
    return m == 0;
}

// ---------------- decode: dst histogram + pos packing ----------------
__global__ void decode_kernel(const void* ei, const float* __restrict__ pos) {
    int i64 = detect_i64((const int*)ei);
    int e = blockIdx.x * blockDim.x + threadIdx.x;
    if (e < N_NODES)
        g_pos4[e] = make_float4(pos[e * 3 + 0], pos[e * 3 + 1], pos[e * 3 + 2], 0.f);
    if (e >= N_EDGES) return;
    int dst;
    if (i64) dst = (int)((const long long*)ei)[N_EDGES + e];
    else     dst = ((const int*)ei)[N_EDGES + e];
    atomicAdd(&g_zero[dst], 1);
}

// ---------------- decoupled-lookback exclusive scan ----------------
__global__ void __launch_bounds__(SCAN_T) scan_kernel() {
    __shared__ int s[SCAN_T];
    __shared__ int s_prefix;
    unsigned long long* state = (unsigned long long*)&g_zero[N_NODES];
    int t = threadIdx.x;
    int part = blockIdx.x;
    int base = part * SCAN_PART + t * SCAN_ITEMS;
    int v[SCAN_ITEMS];
    int tsum = 0;
#pragma unroll
    for (int j = 0; j < SCAN_ITEMS; j++) {
        int idx = base + j;
        v[j] = (idx < N_NODES) ? g_zero[idx] : 0;
        tsum += v[j];
    }
    s[t] = tsum;
    __syncthreads();
#pragma unroll
    for (int off = 1; off < SCAN_T; off <<= 1) {
        int tt = (t >= off) ? s[t - off] : 0;
        __syncthreads();
        s[t] += tt;
        __syncthreads();
    }
    int texcl = s[t] - tsum;
    int btotal = s[SCAN_T - 1];

    if (t == 0) {
        if (part == 0) {
            s_prefix = 0;
            atomicExch(&state[0], (2ULL << 32) | (unsigned)btotal);
        } else {
            atomicExch(&state[part], (1ULL << 32) | (unsigned)btotal);
            int pref = 0;
            int p = part - 1;
            while (true) {
                unsigned long long st;
                do { st = atomicAdd(&state[p], 0ULL); } while ((st >> 32) == 0);
                pref += (int)(unsigned)st;
                if ((st >> 32) == 2) break;
                p--;
            }
            s_prefix = pref;
            atomicExch(&state[part], (2ULL << 32) | (unsigned)(pref + btotal));
        }
    }
    __syncthreads();
    int excl = s_prefix + texcl;
#pragma unroll
    for (int j = 0; j < SCAN_ITEMS; j++) {
        int idx = base + j;
        if (idx < N_NODES) { g_off[idx] = excl; g_cur[idx] = excl; }
        excl += v[j];
    }
}

// ---------------- precompute folded matrices ----------------
__global__ void __launch_bounds__(256) precompute_kernel(
    const float* __restrict__ enc_w2, const float* __restrict__ enc_b2,
    const float* __restrict__ msg_w1, const float* __restrict__ msg_b1,
    const float* __restrict__ msg_w2, const float* __restrict__ msg_b2,
    const float* __restrict__ upd_w1, const float* __restrict__ upd_b1,
    const float* __restrict__ upd_w2, const float* __restrict__ upd_b2,
    const float* __restrict__ out_w, const float* __restrict__ out_b) {
    int b = blockIdx.x;
    int t = threadIdx.x;
    if (b < 13) {
        int l = (b < 12) ? (b % 3) : 2;
        int kind = (b < 12) ? (b / 3) : 4;
        const float* Wp = (l == 0) ? enc_w2 : upd_w2 + (size_t)(l - 1) * 1024;
        const float* L; const float* R; float* P;
        switch (kind) {
            case 0: L = Wp;                      R = msg_w1 + (size_t)l * 2080;        P = c_Pa[l]; break;
            case 1: L = Wp;                      R = msg_w1 + (size_t)l * 2080 + 1024; P = c_Pb[l]; break;
            case 2: L = Wp;                      R = upd_w1 + (size_t)l * 2048;        P = c_P1[l]; break;
            case 3: L = msg_w2 + (size_t)l*1024; R = upd_w1 + (size_t)l * 2048 + 1024; P = c_P2[l]; break;
            default: L = upd_w2 + 2048;          R = out_w;                            P = c_Po;    break;
        }
        for (int e = t; e < 1024; e += 256) {
            int i = e >> 5, j = e & 31;
            float s = 0.f;
            for (int k = 0; k < 32; k++) s = fmaf(L[i * 32 + k], R[k * 32 + j], s);
            P[e] = s;
        }
    } else {
        for (int e = t; e < 416; e += 256) {
            int vid = e >> 5, j = e & 31;
            int l = vid % 3;
            const float* cp = (l == 0) ? enc_b2 : upd_b2 + (size_t)(l - 1) * 32;
            float s = 0.f;
            if (vid < 3) {
                const float* R = msg_w1 + (size_t)l * 2080;
                for (int k = 0; k < 32; k++) s = fmaf(cp[k], R[k * 32 + j], s);
                c_qa[l][j] = s;
            } else if (vid < 6) {
                const float* R = msg_w1 + (size_t)l * 2080 + 1024;
                for (int k = 0; k < 32; k++) s = fmaf(cp[k], R[k * 32 + j], s);
                c_qb[l][j] = s;
            } else if (vid < 9) {
                const float* R = upd_w1 + (size_t)l * 2048;
                for (int k = 0; k < 32; k++) s = fmaf(cp[k], R[k * 32 + j], s);
                c_q1[l][j] = s + upd_b1[l * 32 + j];
            } else if (vid < 12) {
                const float* R = upd_w1 + (size_t)l * 2048 + 1024;
                const float* mb = msg_b2 + (size_t)l * 32;
                for (int k = 0; k < 32; k++) s = fmaf(mb[k], R[k * 32 + j], s);
                c_v[l][j] = s;
            } else {
                const float* ub = upd_b2 + 2 * 32;
                for (int k = 0; k < 32; k++) s = fmaf(ub[k], out_w[k * 32 + j], s);
                c_qo[j] = s + out_b[j];
            }
        }
    }
}

// ---------------- scatter edges into CSR order (by dst) ----------------
__global__ void scatter_kernel(const void* ei) {
    int i64 = detect_i64((const int*)ei);
    int e = blockIdx.x * blockDim.x + threadIdx.x;
    if (e >= N_EDGES) return;
    int src, dst;
    if (i64) {
        const long long* p = (const long long*)ei;
        src = (int)p[e]; dst = (int)p[N_EDGES + e];
    } else {
        const int* p = (const int*)ei;
        src = p[e]; dst = p[N_EDGES + e];
    }
    float4 pd = __ldg(&g_pos4[dst]);
    float4 ps = __ldg(&g_pos4[src]);
    float dx = pd.x - ps.x, dy = pd.y - ps.y, dz = pd.z - ps.z;
    float dist = sqrtf(dx * dx + dy * dy + dz * dz);
    int p = atomicAdd(&g_cur[dst], 1);
    g_epack[p] = make_int2(src, __float_as_int(dist));
}

// ---------------- encoder: h = relu(feat@w1+b1); A=h@Pa0+qa0; B=h@Pb0+qb0 ----------------
__global__ void __launch_bounds__(128) encoder_kernel(
    const float* __restrict__ feat,
    const float* __restrict__ w1, const float* __restrict__ b1) {
    __shared__ float  s_feat[128 * 33];
    __shared__ float4 s_w1[64 * 8];
    __shared__ float4 s_pa[256], s_pb[256];
    __shared__ float4 s_b1[8], s_qa[8], s_qb[8];
    for (int i = threadIdx.x; i < 512; i += 128) s_w1[i] = ((const float4*)w1)[i];
    for (int i = threadIdx.x; i < 256; i += 128) {
        s_pa[i] = ((const float4*)c_Pa[0])[i];
        s_pb[i] = ((const float4*)c_Pb[0])[i];
    }
    if (threadIdx.x < 8) {
        s_b1[threadIdx.x] = ((const float4*)b1)[threadIdx.x];
        s_qa[threadIdx.x] = ((const float4*)c_qa[0])[threadIdx.x];
        s_qb[threadIdx.x] = ((const float4*)c_qb[0])[threadIdx.x];
    }
    __syncthreads();
    int base = blockIdx.x * 128;
    int n = base + threadIdx.x;
    bool act = (n < N_NODES);

    ulonglong2 hacc[8];
#pragma unroll
    for (int i = 0; i < 8; i++) hacc[i] = pack4(s_b1[i]);

#pragma unroll
    for (int half = 0; half < 2; half++) {
        for (int j = threadIdx.x; j < 128 * 32; j += 128) {
            int r = j >> 5, col = j & 31;
            int nn = base + r;
            s_feat[r * 33 + col] =
                (nn < N_NODES) ? feat[(size_t)nn * 64 + half * 32 + col] : 0.f;
        }
        __syncthreads();
        const float* frow = &s_feat[threadIdx.x * 33];
#pragma unroll 8
        for (int k = 0; k < 32; k++) {
            float f = frow[k];
            unsigned long long f2;
            asm("mov.b64 %0, {%1, %1};" : "=l"(f2) : "f"(f));
            const ulonglong2* w = (const ulonglong2*)(s_w1 + (half * 32 + k) * 8);
#pragma unroll
            for (int i = 0; i < 8; i++) {
                ulonglong2 wv = w[i];
                asm("fma.rn.f32x2 %0, %1, %2, %0;" : "+l"(hacc[i].x) : "l"(f2), "l"(wv.x));
                asm("fma.rn.f32x2 %0, %1, %2, %0;" : "+l"(hacc[i].y) : "l"(f2), "l"(wv.y));
            }
        }
        __syncthreads();
    }
    float4 h[8];
#pragma unroll
    for (int i = 0; i < 8; i++) h[i] = relu4(unpack4(hacc[i]));

    ulonglong2 a[8], b[8];
#pragma unroll
    for (int i = 0; i < 8; i++) { a[i] = pack4(s_qa[i]); b[i] = pack4(s_qb[i]); }
    gemv32(s_pa, h, a);
    gemv32(s_pb, h, b);

    if (act) {
        ulonglong2* ph = (ulonglong2*)&g_h[(size_t)n * 8];
        ulonglong2* pa = (ulonglong2*)&g_A[(size_t)n * 8];
#pragma unroll
        for (int i = 0; i < 8; i++) {
            ph[i] = pack4(h[i]);
            pa[i] = a[i];
            g_Bh[(size_t)n * 8 + i] = f4_to_h4(unpack4(b[i]));
        }
    }
}

// ---------------- per layer: agg[n] = sum_e relu(A[n] + B[src_e] + d_e*c + b1) ----------------
__global__ void __launch_bounds__(256) agg_kernel(
    const float* __restrict__ w1c, const float* __restrict__ b1) {
    int n = (blockIdx.x * 256 + threadIdx.x) >> 5;
    if (n >= N_NODES) return;
    int lane = threadIdx.x & 31;
    int c = lane & 7;
    int slot = lane >> 3;

    float4 cv = __ldg(((const float4*)w1c) + c);
    float4 bb = __ldg(((const float4*)b1) + c);

    int start = __ldg(&g_off[n]);
    int end = start + __ldg(&g_zero[n]);   // g_zero = hist

    float4 ab = add4(g_A[(size_t)n * 8 + c], bb);
    float4 acc0 = make_float4(0.f, 0.f, 0.f, 0.f);
    float4 acc1 = make_float4(0.f, 0.f, 0.f, 0.f);

    int i = start + slot;
    for (; i + 4 < end; i += 8) {
        int2 sd0 = __ldg(&g_epack[i]);
        int2 sd1 = __ldg(&g_epack[i + 4]);
        float4 b0 = h4_to_f4(__ldg(&g_Bh[(size_t)sd0.x * 8 + c]));
        float4 b1v = h4_to_f4(__ldg(&g_Bh[(size_t)sd1.x * 8 + c]));
        acc0 = add4(acc0, relu4(fma4(__int_as_float(sd0.y), cv, add4(ab, b0))));
        acc1 = add4(acc1, relu4(fma4(__int_as_float(sd1.y), cv, add4(ab, b1v))));
    }
    if (i < end) {
        int2 sd = __ldg(&g_epack[i]);
        float4 b = h4_to_f4(__ldg(&g_Bh[(size_t)sd.x * 8 + c]));
        acc0 = add4(acc0, relu4(fma4(__int_as_float(sd.y), cv, add4(ab, b))));
    }
    float4 acc = add4(acc0, acc1);
#pragma unroll
    for (int m = 8; m <= 16; m <<= 1) {
        acc.x += __shfl_xor_sync(0xffffffffu, acc.x, m);
        acc.y += __shfl_xor_sync(0xffffffffu, acc.y, m);
        acc.z += __shfl_xor_sync(0xffffffffu, acc.z, m);
        acc.w += __shfl_xor_sync(0xffffffffu, acc.w, m);
    }
    if (lane < 8) g_agg[(size_t)n * 8 + lane] = acc;
}

// ---------------- per layer update (folded) ----------------
__global__ void __launch_bounds__(128) update_kernel(int l, int last, float* __restrict__ outp) {
    __shared__ float4 s_p1[256], s_p2[256], s_pc[256], s_pd[256];
    __shared__ float4 s_q1[8], s_v[8], s_qc[8], s_qd[8];
    {
        const float* P1 = c_P1[l];
        const float* P2 = c_P2[l];
        const float* Pc = last ? c_Po : c_Pa[l + 1 < 3 ? l + 1 : 0];
        const float* Pd = last ? c_Po : c_Pb[l + 1 < 3 ? l + 1 : 0];
        for (int i = threadIdx.x; i < 256; i += 128) {
            s_p1[i] = ((const float4*)P1)[i];
            s_p2[i] = ((const float4*)P2)[i];
            s_pc[i] = ((const float4*)Pc)[i];
            s_pd[i] = ((const float4*)Pd)[i];
        }
        if (threadIdx.x < 8) {
            s_q1[threadIdx.x] = ((const float4*)c_q1[l])[threadIdx.x];
            s_v[threadIdx.x]  = ((const float4*)c_v[l])[threadIdx.x];
            const float* qc = last ? c_qo : c_qa[l + 1 < 3 ? l + 1 : 0];
            const float* qd = last ? c_qo : c_qb[l + 1 < 3 ? l + 1 : 0];
            s_qc[threadIdx.x] = ((const float4*)qc)[threadIdx.x];
            s_qd[threadIdx.x] = ((const float4*)qd)[threadIdx.x];
        }
    }
    __syncthreads();
    int n = blockIdx.x * blockDim.x + threadIdx.x;
    if (n >= N_NODES) return;

    float deg = (float)g_zero[n];
    ulonglong2 uacc[8];
#pragma unroll
    for (int i = 0; i < 8; i++) {
        float4 q = s_q1[i], vv = s_v[i];
        uacc[i] = pack4(make_float4(fmaf(deg, vv.x, q.x), fmaf(deg, vv.y, q.y),
                                    fmaf(deg, vv.z, q.z), fmaf(deg, vv.w, q.w)));
    }
    float4 hr[8];
#pragma unroll
    for (int i = 0; i < 8; i++) hr[i] = g_h[(size_t)n * 8 + i];
    gemv32(s_p1, hr, uacc);
    float4 ar[8];
#pragma unroll
    for (int i = 0; i < 8; i++) ar[i] = g_agg[(size_t)n * 8 + i];
    gemv32(s_p2, ar, uacc);

    float4 u[8];
#pragma unroll
    for (int i = 0; i < 8; i++) u[i] = relu4(unpack4(uacc[i]));

    ulonglong2 cacc[8];
#pragma unroll
    for (int i = 0; i < 8; i++) cacc[i] = pack4(s_qc[i]);
    gemv32(s_pc, u, cacc);

    if (!last) {
        ulonglong2 dacc[8];
#pragma unroll
        for (int i = 0; i < 8; i++) dacc[i] = pack4(s_qd[i]);
        gemv32(s_pd, u, dacc);
        ulonglong2* ph = (ulonglong2*)&g_h[(size_t)n * 8];
        ulonglong2* pa = (ulonglong2*)&g_A[(size_t)n * 8];
#pragma unroll
        for (int i = 0; i < 8; i++) {
            ph[i] = pack4(u[i]);
            pa[i] = cacc[i];
            g_Bh[(size_t)n * 8 + i] = f4_to_h4(unpack4(dacc[i]));
        }
    } else {
        ulonglong2* orow = (ulonglong2*)(outp + (size_t)n * 32);
#pragma unroll
        for (int i = 0; i < 8; i++) orow[i] = cacc[i];
    }
}

// ---------------- launch ----------------
extern "C" void kernel_launch(void* const* d_in, const int* in_sizes, int n_in,
                              void* d_out, int out_size) {
    const float* node_feat = (const float*)d_in[0];
    const float* pos       = (const float*)d_in[1];
    const void*  ei        = d_in[2];
    const float* enc_w1    = (const float*)d_in[3];
    const float* enc_b1    = (const float*)d_in[4];
    const float* enc_w2    = (const float*)d_in[5];
    const float* enc_b2    = (const float*)d_in[6];
    const float* msg_w1    = (const float*)d_in[7];
    const float* msg_b1    = (const float*)d_in[8];
    const float* msg_w2    = (const float*)d_in[9];
    const float* msg_b2    = (const float*)d_in[10];
    const float* upd_w1    = (const float*)d_in[11];
    const float* upd_b1    = (const float*)d_in[12];
    const float* upd_w2    = (const float*)d_in[13];
    const float* upd_b2    = (const float*)d_in[14];
    const float* out_w     = (const float*)d_in[15];
    const float* out_b     = (const float*)d_in[16];
    float* out = (float*)d_out;

    const int NODE_BLOCKS = (N_NODES + 127) / 128;
    const int EDGE_BLOCKS = (N_EDGES + 255) / 256;
    const int AGG_BLOCKS  = (N_NODES * 32 + 255) / 256;

    // fork a side stream for the compute chain (precompute -> encoder),
    // overlapping the CSR-build chain (decode -> scan -> scatter).
    // Host objects only; kernel_launch runs twice (correctness + capture), no leak concern.
    cudaStream_t s1;
    cudaStreamCreateWithFlags(&s1, cudaStreamNonBlocking);
    cudaEvent_t ev_fork, ev_join;
    cudaEventCreateWithFlags(&ev_fork, cudaEventDisableTiming);
    cudaEventCreateWithFlags(&ev_join, cudaEventDisableTiming);

    // fork
    cudaEventRecord(ev_fork, 0);
    cudaStreamWaitEvent(s1, ev_fork, 0);

    // ---- chain B (stream s1): precompute -> encoder ----
    precompute_kernel<<<14, 256, 0, s1>>>(enc_w2, enc_b2, msg_w1, msg_b1, msg_w2, msg_b2,
                                          upd_w1, upd_b1, upd_w2, upd_b2, out_w, out_b);
    encoder_kernel<<<NODE_BLOCKS, 128, 0, s1>>>(node_feat, enc_w1, enc_b1);
    cudaEventRecord(ev_join, s1);

    // ---- chain A (capture stream): memset -> decode -> scan -> scatter ----
    void* p_zero = nullptr;
    cudaGetSymbolAddress(&p_zero, g_zero);
    cudaMemsetAsync(p_zero, 0, (N_NODES + 2 * N_PARTS) * sizeof(int), 0);
    decode_kernel<<<EDGE_BLOCKS, 256>>>(ei, pos);
    scan_kernel<<<N_PARTS, SCAN_T>>>();
    scatter_kernel<<<EDGE_BLOCKS, 256>>>(ei);

    // join
    cudaStreamWaitEvent(0, ev_join, 0);

    for (int l = 0; l < 3; l++) {
        const float* w1 = msg_w1 + (size_t)l * 65 * 32;
        agg_kernel<<<AGG_BLOCKS, 256>>>(w1 + 64 * 32, msg_b1 + (size_t)l * 32);
        update_kernel<<<NODE_BLOCKS, 128>>>(l, l == 2, out);
    }
}